// round 16
// baseline (speedup 1.0000x reference)
#include <cuda_runtime.h>
#include <cstdint>

#define BB 16
#define FF 257
#define TTDIM 1000
#define BF (BB*FF)
#define EPSV 1e-6f
#define EPS2V 1e-6f
#define NPAIR 21

#define NQ (BF*36)
#define NXT (BF*6000)

// chunked smem layout for k_cov: 4 chunks x (3 regions x 6 m x 256 floats)
#define CH_STRIDE 4608      // floats per chunk (3*1536)
#define RG_STRIDE 1536      // floats per region (6*256)
#define M_STRIDE  256
#define SMEM_FLOATS (4*CH_STRIDE)   // 18432 floats = 73728 B

typedef unsigned long long ULL;

// packed f32x2 helpers (sm_100+)
#define FMA_F32X2(d, a, b, c) \
    asm("fma.rn.f32x2 %0, %1, %2, %3;" : "=l"(d) : "l"(a), "l"(b), "l"(c))
#define MUL_F32X2(d, a, b) \
    asm("mul.rn.f32x2 %0, %1, %2;" : "=l"(d) : "l"(a), "l"(b))
#define ADD_F32X2(d, a, b) \
    asm("add.rn.f32x2 %0, %1, %2;" : "=l"(d) : "l"(a), "l"(b))
#define UNPACK_F32X2(lo, hi, s) \
    asm("mov.b64 {%0, %1}, %2;" : "=f"(lo), "=f"(hi) : "l"(s))

__device__ __forceinline__ ULL pk(float lo, float hi) {
    ULL u;
    asm("mov.b64 %0, {%1, %2};" : "=l"(u) : "f"(lo), "f"(hi));
    return u;
}

__device__ __forceinline__ uint32_t smem_u32(const void* p) {
    uint32_t a;
    asm("{ .reg .u64 t; cvta.to.shared.u64 t, %1; cvt.u32.u64 %0, t; }"
        : "=r"(a) : "l"(p));
    return a;
}

__device__ __forceinline__ void cpa16(uint32_t s, const void* g) {
    asm volatile("cp.async.cg.shared.global [%0], [%1], 16;" :: "r"(s), "l"(g));
}

// pair index -> (m, n), n >= m, row-major upper triangle
__host__ __device__ constexpr int PM(int p) {
    return p < 6 ? 0 : p < 11 ? 1 : p < 15 ? 2 : p < 18 ? 3 : p < 20 ? 4 : 5;
}
__host__ __device__ constexpr int PN(int p) {
    return p < 6 ? p : p < 11 ? p - 5 : p < 15 ? p - 9 : p < 18 ? p - 12
         : p < 20 ? p - 14 : 5;
}

// ---------------- scratch (device globals; no runtime allocation) ----------------
__device__ float2 d_V[BF * 216];   // V[bf][k][m][n]
__device__ float2 d_C[BF * 36];    // C[bf][m][n] = sum_t x x^H (unnormalized)
__device__ float2 d_Q[BF * 36];    // working Q
__device__ float  d_part[BF];      // per-(b,f) partial trace(Q C Q^H)
__device__ float  d_sinv[BB];      // 1/scale
__device__ float  d_rs[BB];        // rsqrt(max(scale,1e-6))

// accumulate one chunk from planar smem; warp takes interleaved 32-blocks (half)
template<int P0, int NP>
__device__ __forceinline__ void cov_accum(const float* __restrict__ S, int c,
                                          int len, int t0,
                                          ULL (&acc)[NP][6], ULL (&accC)[NP])
{
    const float* srb = S + c * CH_STRIDE;
    const float* sxr = srb + RG_STRIDE;
    const float* sxi = srb + 2 * RG_STRIDE;
    for (int t = t0; t < len; t += 64) {
        float xr6[6], xi6[6];
        ULL rv2[6];
        #pragma unroll
        for (int m = 0; m < 6; ++m) {
            xr6[m] = sxr[m * M_STRIDE + t];
            xi6[m] = sxi[m * M_STRIDE + t];
            float rk = srb[m * M_STRIDE + t];
            rv2[m] = pk(rk, rk);
        }
        #pragma unroll
        for (int j = 0; j < NP; ++j) {
            const int m = PM(P0 + j), n = PN(P0 + j);
            // cr = (crR, crI): crR = ax*bx + ay*by ; crI = ay*bx - ax*by
            ULL axy = pk(xr6[m],  xi6[m]);
            ULL ayx = pk(xi6[m], -xr6[m]);
            ULL bxx = pk(xr6[n],  xr6[n]);
            ULL byy = pk(xi6[n],  xi6[n]);
            ULL cr;
            MUL_F32X2(cr, ayx, byy);
            FMA_F32X2(cr, axy, bxx, cr);
            ADD_F32X2(accC[j], accC[j], cr);
            #pragma unroll
            for (int k = 0; k < 6; ++k)
                FMA_F32X2(acc[j][k], rv2[k], cr, acc[j][k]);
        }
    }
}

// per-warp main: pipelined chunk waits (CONVERGED barriers: all 256 threads
// execute exactly this sequence once), then in-register butterfly reduction
// and lane-0 store to the per-warp output row.
template<int P0, int NP>
__device__ __forceinline__ void cov_main(const float* __restrict__ S,
                                         int half, int lane, float* outrow)
{
    ULL acc[NP][6];
    ULL accC[NP];
    #pragma unroll
    for (int j = 0; j < NP; ++j) {
        accC[j] = 0;
        #pragma unroll
        for (int k = 0; k < 6; ++k) acc[j][k] = 0;
    }
    const int t0 = lane + 32 * half;

    asm volatile("cp.async.wait_group 3;" ::: "memory");
    __syncthreads();
    cov_accum<P0, NP>(S, 0, 256, t0, acc, accC);
    asm volatile("cp.async.wait_group 2;" ::: "memory");
    __syncthreads();
    cov_accum<P0, NP>(S, 1, 256, t0, acc, accC);
    asm volatile("cp.async.wait_group 1;" ::: "memory");
    __syncthreads();
    cov_accum<P0, NP>(S, 2, 256, t0, acc, accC);
    asm volatile("cp.async.wait_group 0;" ::: "memory");
    __syncthreads();
    cov_accum<P0, NP>(S, 3, 232, t0, acc, accC);

    // butterfly reduce across the 32 lanes (packed 64-bit adds)
    #pragma unroll
    for (int o = 16; o; o >>= 1) {
        #pragma unroll
        for (int j = 0; j < NP; ++j) {
            ULL v = __shfl_xor_sync(0xffffffffu, accC[j], o);
            ADD_F32X2(accC[j], accC[j], v);
            #pragma unroll
            for (int k = 0; k < 6; ++k) {
                ULL w = __shfl_xor_sync(0xffffffffu, acc[j][k], o);
                ADD_F32X2(acc[j][k], acc[j][k], w);
            }
        }
    }
    if (lane == 0) {
        #pragma unroll
        for (int j = 0; j < NP; ++j) {
            #pragma unroll
            for (int k = 0; k < 6; ++k) {
                float aR, aI;
                UNPACK_F32X2(aR, aI, acc[j][k]);
                outrow[j * 16 + k]     = aR;
                outrow[j * 16 + 6 + k] = aI;
            }
            float cR, cI;
            UNPACK_F32X2(cR, cI, accC[j]);
            outrow[j * 16 + 12] = cR;
            outrow[j * 16 + 13] = cI;
        }
    }
}

// ---------------- K1: weighted covariances V, plain covariance C, Q copy ----------
// 256 threads: warp w -> pair group pg = (w<4 ? w : 7-w), t-half h = w>>2.
__global__ __launch_bounds__(256, 2) void k_cov(
    const float* __restrict__ r,
    const float* __restrict__ Qre, const float* __restrict__ Qim,
    const float* __restrict__ xre, const float* __restrict__ xim)
{
    extern __shared__ float smem[];          // 18432-float tile
    __shared__ float swp[8][96];             // per-warp reduced partials

    const int bf  = blockIdx.x;
    const int tid = threadIdx.x;
    const int wid = tid >> 5, lane = tid & 31;
    const size_t base = (size_t)bf * 6000;
    const uint32_t sbase = smem_u32(smem);

    if (tid < 36) {
        const size_t qi = (size_t)bf * 36 + tid;
        d_Q[qi] = make_float2(Qre[qi], Qim[qi]);
    }

    // issue all 4 chunk groups up front (16B cp.async, rows 16B-aligned)
    #pragma unroll
    for (int c = 0; c < 4; ++c) {
        const int len  = (c == 3) ? 232 : 256;
        const int len4 = len >> 2;            // float4 per (region, m) row
        const int nf4  = 18 * len4;           // 3 regions x 6 m
        for (int i = tid; i < nf4; i += 256) {
            const int row = i / len4, j = i % len4;
            const int region = row / 6, m = row % 6;
            const float* sp = (region == 0) ? r : (region == 1) ? xre : xim;
            const float* g  = sp + base + m * 1000 + 256 * c + 4 * j;
            const uint32_t s = sbase +
                4u * (c * CH_STRIDE + region * RG_STRIDE + m * M_STRIDE + 4 * j);
            cpa16(s, g);
        }
        asm volatile("cp.async.commit_group;" ::: "memory");
    }

    const int pg   = (wid < 4) ? wid : 7 - wid;
    const int half = wid >> 2;
    if      (pg == 0) cov_main<0, 6>(smem, half, lane, swp[wid]);
    else if (pg == 1) cov_main<6, 5>(smem, half, lane, swp[wid]);
    else if (pg == 2) cov_main<11,5>(smem, half, lane, swp[wid]);
    else              cov_main<16,5>(smem, half, lane, swp[wid]);
    __syncthreads();   // all warp partials in swp

    // combine halves: 294 scalars = 21 pairs x 14 comps (STRIDED: block has 256 threads)
    for (int s = tid; s < 294; s += 256) {
        const int pair = s / 14, comp = s % 14;
        const int g = pair < 6 ? 0 : pair < 11 ? 1 : pair < 16 ? 2 : 3;
        const int j = pair - (g == 0 ? 0 : g == 1 ? 6 : g == 2 ? 11 : 16);
        swp[g][j * 16 + comp] += swp[7 - g][j * 16 + comp];
    }
    __syncthreads();

    if (tid < NPAIR) {
        const int g = tid < 6 ? 0 : tid < 11 ? 1 : tid < 16 ? 2 : 3;
        const int j = tid - (g == 0 ? 0 : g == 1 ? 6 : g == 2 ? 11 : 16);
        const float* s = swp[g] + j * 16;
        const int m = PM(tid), n = PN(tid);
        const float invT = 1.0f / (float)TTDIM;
        float2* Vg = d_V + (size_t)bf * 216;
        #pragma unroll
        for (int k = 0; k < 6; ++k) {
            float vr = s[k] * invT + ((m == n) ? EPSV : 0.f);
            float vi = s[6 + k] * invT;
            Vg[(k * 6 + m) * 6 + n] = make_float2(vr,  vi);
            Vg[(k * 6 + n) * 6 + m] = make_float2(vr, -vi);
        }
        float2* Cg = d_C + (size_t)bf * 36;
        Cg[m * 6 + n] = make_float2(s[12],  s[13]);
        Cg[n * 6 + m] = make_float2(s[12], -s[13]);
    }
}

// ---------------- K2: one ISS iteration, single warp per (b,f) --------------------
__global__ __launch_bounds__(32) void k_iss(int apply_pre)
{
    __shared__ float2 sV[216], sC[36], sQ[36], sVq[36], sv[6], sq[6];
    const int bf = blockIdx.x, b = bf / FF;
    const int lane = threadIdx.x;

    for (int i = lane; i < 216; i += 32) sV[i] = d_V[(size_t)bf * 216 + i];
    const float rs = apply_pre ? d_rs[b] : 1.0f;
    for (int i = lane; i < 36; i += 32) {
        sC[i] = d_C[(size_t)bf * 36 + i];
        float2 q = d_Q[(size_t)bf * 36 + i];
        sQ[i] = make_float2(q.x * rs, q.y * rs);
    }
    __syncwarp();

    for (int k = 0; k < 6; ++k) {
        if (lane < 6) sq[lane] = sQ[k * 6 + lane];       // snapshot row k
        __syncwarp();
        for (int it = lane; it < 36; it += 32) {          // Vq = V * conj(q)
            const int kk = it / 6, m = it % 6;
            float ar = 0.f, ai = 0.f;
            #pragma unroll
            for (int n = 0; n < 6; ++n) {
                float2 V = sV[(kk * 6 + m) * 6 + n];
                float2 q = sq[n];
                ar += V.x * q.x + V.y * q.y;
                ai += V.y * q.x - V.x * q.y;
            }
            sVq[it] = make_float2(ar, ai);
        }
        __syncwarp();
        if (lane < 6) {
            const int kk = lane;
            float qvq = 0.f, nr = 0.f, ni = 0.f;
            #pragma unroll
            for (int m = 0; m < 6; ++m) {
                float2 q = sq[m], Vq = sVq[kk * 6 + m], Qe = sQ[kk * 6 + m];
                qvq += q.x * Vq.x - q.y * Vq.y;
                nr  += Qe.x * Vq.x - Qe.y * Vq.y;
                ni  += Qe.x * Vq.y + Qe.y * Vq.x;
            }
            qvq = fmaxf(qvq, EPS2V);
            const float inv = 1.0f / qvq;
            float2 vv = make_float2(nr * inv, ni * inv);
            if (kk == k) vv = make_float2(1.0f - rsqrtf(qvq), 0.f);
            sv[kk] = vv;
        }
        __syncwarp();
        for (int it = lane; it < 36; it += 32) {          // Q -= v outer q
            const int kk = it / 6, m = it % 6;
            float2 vv = sv[kk], q = sq[m], Qe = sQ[it];
            Qe.x -= vv.x * q.x - vv.y * q.y;
            Qe.y -= vv.x * q.y + vv.y * q.x;
            sQ[it] = Qe;
        }
        __syncwarp();
    }

    // trace(Q C Q^H)
    for (int it = lane; it < 36; it += 32) {
        const int m = it / 6, n = it % 6;
        float ar = 0.f, ai = 0.f;
        #pragma unroll
        for (int p = 0; p < 6; ++p) {
            float2 a = sQ[m * 6 + p], c = sC[p * 6 + n];
            ar += a.x * c.x - a.y * c.y;
            ai += a.x * c.y + a.y * c.x;
        }
        sVq[it] = make_float2(ar, ai);
    }
    __syncwarp();
    float s = 0.f;
    for (int it = lane; it < 36; it += 32) {
        float2 qc = sVq[it], q = sQ[it];
        s += qc.x * q.x + qc.y * q.y;
    }
    #pragma unroll
    for (int o = 16; o; o >>= 1) s += __shfl_down_sync(0xffffffffu, s, o);
    if (lane == 0) d_part[bf] = s;
    for (int i = lane; i < 36; i += 32) d_Q[(size_t)bf * 36 + i] = sQ[i];
}

// ---------------- K3: per-batch scale from trace partials -------------------------
__global__ __launch_bounds__(256) void k_scale()
{
    __shared__ float red[256];
    const int b = blockIdx.x, tid = threadIdx.x;
    float s = 0.f;
    for (int i = tid; i < FF; i += 256) s += d_part[b * FF + i];
    red[tid] = s;
    __syncthreads();
    for (int o = 128; o > 0; o >>= 1) {
        if (tid < o) red[tid] += red[tid + o];
        __syncthreads();
    }
    if (tid == 0) {
        const float scale = red[0] / (float)(FF * 6 * TTDIM);
        d_sinv[b] = 1.0f / scale;
        d_rs[b]   = rsqrtf(fmaxf(scale, 1e-6f));
    }
}

// ---------------- K4: final Q output + xt = |Q2 x|^2 / scale2 ---------------------
__global__ __launch_bounds__(256) void k_final(
    const float* __restrict__ xre, const float* __restrict__ xim,
    float* __restrict__ out)
{
    __shared__ float sQr[36], sQi[36];
    __shared__ float sI;
    const int bf = blockIdx.x, b = bf / FF, tid = threadIdx.x;
    if (tid < 36) {
        float2 q = d_Q[(size_t)bf * 36 + tid];
        sQr[tid] = q.x;
        sQi[tid] = q.y;
        out[(size_t)bf * 36 + tid] = q.x * d_rs[b];
    }
    if (tid == 64) sI = d_sinv[b];
    __syncthreads();

    if (tid < 250) {
        const size_t base = (size_t)bf * 6000;
        const float4* xr4 = reinterpret_cast<const float4*>(xre + base);
        const float4* xi4 = reinterpret_cast<const float4*>(xim + base);
        float4* xt4 = reinterpret_cast<float4*>(out + (size_t)NQ + base);
        const float inv = sI;

        float4 vr[6], vi[6];
        #pragma unroll
        for (int n = 0; n < 6; ++n) {
            vr[n] = xr4[n * 250 + tid];
            vi[n] = xi4[n * 250 + tid];
        }
        #pragma unroll
        for (int m = 0; m < 6; ++m) {
            float4 ar = make_float4(0,0,0,0), ai = make_float4(0,0,0,0);
            #pragma unroll
            for (int n = 0; n < 6; ++n) {
                const float qr = sQr[m * 6 + n], qi = sQi[m * 6 + n];
                ar.x = fmaf(qr, vr[n].x, fmaf(-qi, vi[n].x, ar.x));
                ar.y = fmaf(qr, vr[n].y, fmaf(-qi, vi[n].y, ar.y));
                ar.z = fmaf(qr, vr[n].z, fmaf(-qi, vi[n].z, ar.z));
                ar.w = fmaf(qr, vr[n].w, fmaf(-qi, vi[n].w, ar.w));
                ai.x = fmaf(qr, vi[n].x, fmaf(qi, vr[n].x, ai.x));
                ai.y = fmaf(qr, vi[n].y, fmaf(qi, vr[n].y, ai.y));
                ai.z = fmaf(qr, vi[n].z, fmaf(qi, vr[n].z, ai.z));
                ai.w = fmaf(qr, vi[n].w, fmaf(qi, vr[n].w, ai.w));
            }
            float4 o4;
            o4.x = (ar.x * ar.x + ai.x * ai.x) * inv;
            o4.y = (ar.y * ar.y + ai.y * ai.y) * inv;
            o4.z = (ar.z * ar.z + ai.z * ai.z) * inv;
            o4.w = (ar.w * ar.w + ai.w * ai.w) * inv;
            xt4[m * 250 + tid] = o4;
        }
    }
}

// ---------------- launch ----------------
extern "C" void kernel_launch(void* const* d_in, const int* in_sizes, int n_in,
                              void* d_out, int out_size)
{
    const float* r   = (const float*)d_in[0];
    const float* Qre = (const float*)d_in[1];
    const float* Qim = (const float*)d_in[2];
    const float* xre = (const float*)d_in[3];
    const float* xim = (const float*)d_in[4];
    float* out = (float*)d_out;

    const int smem_cov = SMEM_FLOATS * (int)sizeof(float);   // 73728 B
    cudaFuncSetAttribute(k_cov, cudaFuncAttributeMaxDynamicSharedMemorySize, smem_cov);

    k_cov<<<BF, 256, smem_cov>>>(r, Qre, Qim, xre, xim);
    k_iss<<<BF, 32>>>(0);
    k_scale<<<BB, 256>>>();
    k_iss<<<BF, 32>>>(1);
    k_scale<<<BB, 256>>>();
    k_final<<<BF, 256>>>(xre, xim, out);
}

// round 17
// speedup vs baseline: 1.0975x; 1.0975x over previous
#include <cuda_runtime.h>
#include <cstdint>

#define BB 16
#define FF 257
#define TTDIM 1000
#define BF (BB*FF)
#define EPSV 1e-6f
#define EPS2V 1e-6f
#define NPAIR 21

#define NQ (BF*36)
#define NXT (BF*6000)

// chunked smem layout for k_cov: 4 chunks x (3 regions x 6 m x 256 floats)
#define CH_STRIDE 4608      // floats per chunk (3*1536)
#define RG_STRIDE 1536      // floats per region (6*256)
#define M_STRIDE  256
#define SMEM_FLOATS (4*CH_STRIDE)   // 18432 floats = 73728 B

typedef unsigned long long ULL;

// packed f32x2 helpers (sm_100+)
#define FMA_F32X2(d, a, b, c) \
    asm("fma.rn.f32x2 %0, %1, %2, %3;" : "=l"(d) : "l"(a), "l"(b), "l"(c))
#define MUL_F32X2(d, a, b) \
    asm("mul.rn.f32x2 %0, %1, %2;" : "=l"(d) : "l"(a), "l"(b))
#define ADD_F32X2(d, a, b) \
    asm("add.rn.f32x2 %0, %1, %2;" : "=l"(d) : "l"(a), "l"(b))
#define UNPACK_F32X2(lo, hi, s) \
    asm("mov.b64 {%0, %1}, %2;" : "=f"(lo), "=f"(hi) : "l"(s))

__device__ __forceinline__ ULL pk(float lo, float hi) {
    ULL u;
    asm("mov.b64 %0, {%1, %2};" : "=l"(u) : "f"(lo), "f"(hi));
    return u;
}

__device__ __forceinline__ uint32_t smem_u32(const void* p) {
    uint32_t a;
    asm("{ .reg .u64 t; cvta.to.shared.u64 t, %1; cvt.u32.u64 %0, t; }"
        : "=r"(a) : "l"(p));
    return a;
}

__device__ __forceinline__ void cpa16(uint32_t s, const void* g) {
    asm volatile("cp.async.cg.shared.global [%0], [%1], 16;" :: "r"(s), "l"(g));
}

// pair index -> (m, n), n >= m, row-major upper triangle
__host__ __device__ constexpr int PM(int p) {
    return p < 6 ? 0 : p < 11 ? 1 : p < 15 ? 2 : p < 18 ? 3 : p < 20 ? 4 : 5;
}
__host__ __device__ constexpr int PN(int p) {
    return p < 6 ? p : p < 11 ? p - 5 : p < 15 ? p - 9 : p < 18 ? p - 12
         : p < 20 ? p - 14 : 5;
}

// ---------------- scratch (device globals; no runtime allocation) ----------------
__device__ float2 d_V[BF * 216];   // V[bf][k][m][n]
__device__ float2 d_C[BF * 36];    // C[bf][m][n] = sum_t x x^H (unnormalized)
__device__ float2 d_Q[BF * 36];    // working Q
__device__ float  d_part[BF];      // per-(b,f) partial trace(Q C Q^H)
__device__ float  d_sinv[BB];      // 1/scale
__device__ float  d_rs[BB];        // rsqrt(max(scale,1e-6))

// accumulate one chunk from planar smem; warp sweeps all t (stride 32).
// Per-t channel packs hoisted out of the pair loop (DCE trims unused).
template<int P0, int NP>
__device__ __forceinline__ void cov_accum(const float* __restrict__ S, int c,
                                          int len, int lane,
                                          ULL (&acc)[NP][6], ULL (&accC)[NP])
{
    const float* srb = S + c * CH_STRIDE;
    const float* sxr = srb + RG_STRIDE;
    const float* sxi = srb + 2 * RG_STRIDE;
    for (int t = lane; t < len; t += 32) {
        float xr6[6], xi6[6];
        ULL rv2[6];
        #pragma unroll
        for (int m = 0; m < 6; ++m) {
            xr6[m] = sxr[m * M_STRIDE + t];
            xi6[m] = sxi[m * M_STRIDE + t];
            float rk = srb[m * M_STRIDE + t];
            rv2[m] = pk(rk, rk);
        }
        // hoisted packs; unused entries dead-code-eliminated per instantiation
        ULL axy[6], ayx[6], bxx[6], byy[6];
        #pragma unroll
        for (int m = 0; m < 6; ++m) {
            axy[m] = pk(xr6[m],  xi6[m]);
            ayx[m] = pk(xi6[m], -xr6[m]);
            bxx[m] = pk(xr6[m],  xr6[m]);
            byy[m] = pk(xi6[m],  xi6[m]);
        }
        #pragma unroll
        for (int j = 0; j < NP; ++j) {
            const int m = PM(P0 + j), n = PN(P0 + j);
            // cr = (crR, crI): crR = ax*bx + ay*by ; crI = ay*bx - ax*by
            ULL cr;
            MUL_F32X2(cr, ayx[m], byy[n]);
            FMA_F32X2(cr, axy[m], bxx[n], cr);
            ADD_F32X2(accC[j], accC[j], cr);
            #pragma unroll
            for (int k = 0; k < 6; ++k)
                FMA_F32X2(acc[j][k], rv2[k], cr, acc[j][k]);
        }
    }
}

// per-warp main: pipelined chunk waits (CONVERGED barriers: all 128 threads
// execute exactly this sequence once), then in-register butterfly reduction
// and lane-0 store to the per-warp output row.
template<int P0, int NP>
__device__ __forceinline__ void cov_main(const float* __restrict__ S,
                                         int lane, float* outrow)
{
    ULL acc[NP][6];
    ULL accC[NP];
    #pragma unroll
    for (int j = 0; j < NP; ++j) {
        accC[j] = 0;
        #pragma unroll
        for (int k = 0; k < 6; ++k) acc[j][k] = 0;
    }

    asm volatile("cp.async.wait_group 3;" ::: "memory");
    __syncthreads();
    cov_accum<P0, NP>(S, 0, 256, lane, acc, accC);
    asm volatile("cp.async.wait_group 2;" ::: "memory");
    __syncthreads();
    cov_accum<P0, NP>(S, 1, 256, lane, acc, accC);
    asm volatile("cp.async.wait_group 1;" ::: "memory");
    __syncthreads();
    cov_accum<P0, NP>(S, 2, 256, lane, acc, accC);
    asm volatile("cp.async.wait_group 0;" ::: "memory");
    __syncthreads();
    cov_accum<P0, NP>(S, 3, 232, lane, acc, accC);

    // butterfly reduce across the 32 lanes (packed 64-bit adds)
    #pragma unroll
    for (int o = 16; o; o >>= 1) {
        #pragma unroll
        for (int j = 0; j < NP; ++j) {
            ULL v = __shfl_xor_sync(0xffffffffu, accC[j], o);
            ADD_F32X2(accC[j], accC[j], v);
            #pragma unroll
            for (int k = 0; k < 6; ++k) {
                ULL w = __shfl_xor_sync(0xffffffffu, acc[j][k], o);
                ADD_F32X2(acc[j][k], acc[j][k], w);
            }
        }
    }
    if (lane == 0) {
        #pragma unroll
        for (int j = 0; j < NP; ++j) {
            #pragma unroll
            for (int k = 0; k < 6; ++k) {
                float aR, aI;
                UNPACK_F32X2(aR, aI, acc[j][k]);
                outrow[j * 16 + k]     = aR;
                outrow[j * 16 + 6 + k] = aI;
            }
            float cR, cI;
            UNPACK_F32X2(cR, cI, accC[j]);
            outrow[j * 16 + 12] = cR;
            outrow[j * 16 + 13] = cI;
        }
    }
}

// ---------------- K1: weighted covariances V, plain covariance C, Q copy ----------
// 128 threads (4 warps, pair groups {6,5,5,5}), 3 blocks/SM for latency hiding.
__global__ __launch_bounds__(128, 3) void k_cov(
    const float* __restrict__ r,
    const float* __restrict__ Qre, const float* __restrict__ Qim,
    const float* __restrict__ xre, const float* __restrict__ xim)
{
    extern __shared__ float smem[];          // 18432-float tile
    __shared__ float swp[4][96];             // per-warp reduced partials

    const int bf  = blockIdx.x;
    const int tid = threadIdx.x;
    const int wid = tid >> 5, lane = tid & 31;
    const size_t base = (size_t)bf * 6000;
    const uint32_t sbase = smem_u32(smem);

    if (tid < 36) {
        const size_t qi = (size_t)bf * 36 + tid;
        d_Q[qi] = make_float2(Qre[qi], Qim[qi]);
    }

    // issue all 4 chunk groups up front (16B cp.async, rows 16B-aligned)
    #pragma unroll
    for (int c = 0; c < 4; ++c) {
        const int len  = (c == 3) ? 232 : 256;
        const int len4 = len >> 2;            // float4 per (region, m) row
        const int nf4  = 18 * len4;           // 3 regions x 6 m
        for (int i = tid; i < nf4; i += 128) {
            const int row = i / len4, j = i % len4;
            const int region = row / 6, m = row % 6;
            const float* sp = (region == 0) ? r : (region == 1) ? xre : xim;
            const float* g  = sp + base + m * 1000 + 256 * c + 4 * j;
            const uint32_t s = sbase +
                4u * (c * CH_STRIDE + region * RG_STRIDE + m * M_STRIDE + 4 * j);
            cpa16(s, g);
        }
        asm volatile("cp.async.commit_group;" ::: "memory");
    }

    if      (wid == 0) cov_main<0, 6>(smem, lane, swp[0]);
    else if (wid == 1) cov_main<6, 5>(smem, lane, swp[1]);
    else if (wid == 2) cov_main<11,5>(smem, lane, swp[2]);
    else               cov_main<16,5>(smem, lane, swp[3]);
    __syncthreads();   // all warp partials in swp

    if (tid < NPAIR) {
        const int g = tid < 6 ? 0 : tid < 11 ? 1 : tid < 16 ? 2 : 3;
        const int j = tid - (g == 0 ? 0 : g == 1 ? 6 : g == 2 ? 11 : 16);
        const float* s = swp[g] + j * 16;
        const int m = PM(tid), n = PN(tid);
        const float invT = 1.0f / (float)TTDIM;
        float2* Vg = d_V + (size_t)bf * 216;
        #pragma unroll
        for (int k = 0; k < 6; ++k) {
            float vr = s[k] * invT + ((m == n) ? EPSV : 0.f);
            float vi = s[6 + k] * invT;
            Vg[(k * 6 + m) * 6 + n] = make_float2(vr,  vi);
            Vg[(k * 6 + n) * 6 + m] = make_float2(vr, -vi);
        }
        float2* Cg = d_C + (size_t)bf * 36;
        Cg[m * 6 + n] = make_float2(s[12],  s[13]);
        Cg[n * 6 + m] = make_float2(s[12], -s[13]);
    }
}

// ---------------- K2: one ISS iteration, single warp per (b,f) --------------------
__global__ __launch_bounds__(32) void k_iss(int apply_pre)
{
    __shared__ float2 sV[216], sC[36], sQ[36], sVq[36], sv[6], sq[6];
    const int bf = blockIdx.x, b = bf / FF;
    const int lane = threadIdx.x;

    for (int i = lane; i < 216; i += 32) sV[i] = d_V[(size_t)bf * 216 + i];
    const float rs = apply_pre ? d_rs[b] : 1.0f;
    for (int i = lane; i < 36; i += 32) {
        sC[i] = d_C[(size_t)bf * 36 + i];
        float2 q = d_Q[(size_t)bf * 36 + i];
        sQ[i] = make_float2(q.x * rs, q.y * rs);
    }
    __syncwarp();

    for (int k = 0; k < 6; ++k) {
        if (lane < 6) sq[lane] = sQ[k * 6 + lane];       // snapshot row k
        __syncwarp();
        for (int it = lane; it < 36; it += 32) {          // Vq = V * conj(q)
            const int kk = it / 6, m = it % 6;
            float ar = 0.f, ai = 0.f;
            #pragma unroll
            for (int n = 0; n < 6; ++n) {
                float2 V = sV[(kk * 6 + m) * 6 + n];
                float2 q = sq[n];
                ar += V.x * q.x + V.y * q.y;
                ai += V.y * q.x - V.x * q.y;
            }
            sVq[it] = make_float2(ar, ai);
        }
        __syncwarp();
        if (lane < 6) {
            const int kk = lane;
            float qvq = 0.f, nr = 0.f, ni = 0.f;
            #pragma unroll
            for (int m = 0; m < 6; ++m) {
                float2 q = sq[m], Vq = sVq[kk * 6 + m], Qe = sQ[kk * 6 + m];
                qvq += q.x * Vq.x - q.y * Vq.y;
                nr  += Qe.x * Vq.x - Qe.y * Vq.y;
                ni  += Qe.x * Vq.y + Qe.y * Vq.x;
            }
            qvq = fmaxf(qvq, EPS2V);
            const float inv = 1.0f / qvq;
            float2 vv = make_float2(nr * inv, ni * inv);
            if (kk == k) vv = make_float2(1.0f - rsqrtf(qvq), 0.f);
            sv[kk] = vv;
        }
        __syncwarp();
        for (int it = lane; it < 36; it += 32) {          // Q -= v outer q
            const int kk = it / 6, m = it % 6;
            float2 vv = sv[kk], q = sq[m], Qe = sQ[it];
            Qe.x -= vv.x * q.x - vv.y * q.y;
            Qe.y -= vv.x * q.y + vv.y * q.x;
            sQ[it] = Qe;
        }
        __syncwarp();
    }

    // trace(Q C Q^H)
    for (int it = lane; it < 36; it += 32) {
        const int m = it / 6, n = it % 6;
        float ar = 0.f, ai = 0.f;
        #pragma unroll
        for (int p = 0; p < 6; ++p) {
            float2 a = sQ[m * 6 + p], c = sC[p * 6 + n];
            ar += a.x * c.x - a.y * c.y;
            ai += a.x * c.y + a.y * c.x;
        }
        sVq[it] = make_float2(ar, ai);
    }
    __syncwarp();
    float s = 0.f;
    for (int it = lane; it < 36; it += 32) {
        float2 qc = sVq[it], q = sQ[it];
        s += qc.x * q.x + qc.y * q.y;
    }
    #pragma unroll
    for (int o = 16; o; o >>= 1) s += __shfl_down_sync(0xffffffffu, s, o);
    if (lane == 0) d_part[bf] = s;
    for (int i = lane; i < 36; i += 32) d_Q[(size_t)bf * 36 + i] = sQ[i];
}

// ---------------- K3: per-batch scale from trace partials -------------------------
__global__ __launch_bounds__(256) void k_scale()
{
    __shared__ float red[256];
    const int b = blockIdx.x, tid = threadIdx.x;
    float s = 0.f;
    for (int i = tid; i < FF; i += 256) s += d_part[b * FF + i];
    red[tid] = s;
    __syncthreads();
    for (int o = 128; o > 0; o >>= 1) {
        if (tid < o) red[tid] += red[tid + o];
        __syncthreads();
    }
    if (tid == 0) {
        const float scale = red[0] / (float)(FF * 6 * TTDIM);
        d_sinv[b] = 1.0f / scale;
        d_rs[b]   = rsqrtf(fmaxf(scale, 1e-6f));
    }
}

// ---------------- K4: final Q output + xt = |Q2 x|^2 / scale2 ---------------------
__global__ __launch_bounds__(256) void k_final(
    const float* __restrict__ xre, const float* __restrict__ xim,
    float* __restrict__ out)
{
    __shared__ float sQr[36], sQi[36];
    __shared__ float sI;
    const int bf = blockIdx.x, b = bf / FF, tid = threadIdx.x;
    if (tid < 36) {
        float2 q = d_Q[(size_t)bf * 36 + tid];
        sQr[tid] = q.x;
        sQi[tid] = q.y;
        out[(size_t)bf * 36 + tid] = q.x * d_rs[b];
    }
    if (tid == 64) sI = d_sinv[b];
    __syncthreads();

    if (tid < 250) {
        const size_t base = (size_t)bf * 6000;
        const float4* xr4 = reinterpret_cast<const float4*>(xre + base);
        const float4* xi4 = reinterpret_cast<const float4*>(xim + base);
        float4* xt4 = reinterpret_cast<float4*>(out + (size_t)NQ + base);
        const float inv = sI;

        float4 vr[6], vi[6];
        #pragma unroll
        for (int n = 0; n < 6; ++n) {
            vr[n] = xr4[n * 250 + tid];
            vi[n] = xi4[n * 250 + tid];
        }
        #pragma unroll
        for (int m = 0; m < 6; ++m) {
            float4 ar = make_float4(0,0,0,0), ai = make_float4(0,0,0,0);
            #pragma unroll
            for (int n = 0; n < 6; ++n) {
                const float qr = sQr[m * 6 + n], qi = sQi[m * 6 + n];
                ar.x = fmaf(qr, vr[n].x, fmaf(-qi, vi[n].x, ar.x));
                ar.y = fmaf(qr, vr[n].y, fmaf(-qi, vi[n].y, ar.y));
                ar.z = fmaf(qr, vr[n].z, fmaf(-qi, vi[n].z, ar.z));
                ar.w = fmaf(qr, vr[n].w, fmaf(-qi, vi[n].w, ar.w));
                ai.x = fmaf(qr, vi[n].x, fmaf(qi, vr[n].x, ai.x));
                ai.y = fmaf(qr, vi[n].y, fmaf(qi, vr[n].y, ai.y));
                ai.z = fmaf(qr, vi[n].z, fmaf(qi, vr[n].z, ai.z));
                ai.w = fmaf(qr, vi[n].w, fmaf(qi, vr[n].w, ai.w));
            }
            float4 o4;
            o4.x = (ar.x * ar.x + ai.x * ai.x) * inv;
            o4.y = (ar.y * ar.y + ai.y * ai.y) * inv;
            o4.z = (ar.z * ar.z + ai.z * ai.z) * inv;
            o4.w = (ar.w * ar.w + ai.w * ai.w) * inv;
            xt4[m * 250 + tid] = o4;
        }
    }
}

// ---------------- launch ----------------
extern "C" void kernel_launch(void* const* d_in, const int* in_sizes, int n_in,
                              void* d_out, int out_size)
{
    const float* r   = (const float*)d_in[0];
    const float* Qre = (const float*)d_in[1];
    const float* Qim = (const float*)d_in[2];
    const float* xre = (const float*)d_in[3];
    const float* xim = (const float*)d_in[4];
    float* out = (float*)d_out;

    const int smem_cov = SMEM_FLOATS * (int)sizeof(float);   // 73728 B
    cudaFuncSetAttribute(k_cov, cudaFuncAttributeMaxDynamicSharedMemorySize, smem_cov);

    k_cov<<<BF, 128, smem_cov>>>(r, Qre, Qim, xre, xim);
    k_iss<<<BF, 32>>>(0);
    k_scale<<<BB, 256>>>();
    k_iss<<<BF, 32>>>(1);
    k_scale<<<BB, 256>>>();
    k_final<<<BF, 256>>>(xre, xim, out);
}